// round 11
// baseline (speedup 1.0000x reference)
#include <cuda_runtime.h>
#include <math.h>

#define PH 7
#define PW 7
#define NB 4
#define NH 64
#define NW 64
#define NC 256
#define NR 128
#define NC4 (NC / 4)   // 64 float4 lanes per cell
#define NSL 4          // y-slices per CTA

// Scratch: sliding 2x2 max pyramid, q[b][y][x][c4] (float4) = max over
// fm[y..y+1][x..x+1] (clamped). 16 MB, L2-resident.
__device__ float4 g_q[NB * NH * NW * NC4];

__device__ __forceinline__ float4 f4max(float4 a, float4 b) {
    float4 r;
    r.x = fmaxf(a.x, b.x);
    r.y = fmaxf(a.y, b.y);
    r.z = fmaxf(a.z, b.z);
    r.w = fmaxf(a.w, b.w);
    return r;
}

// ---------------- Kernel 1: build 2x2 sliding-max pyramid ----------------
__global__ void __launch_bounds__(256)
build_q_kernel(const float4* __restrict__ fm) {
    int o = blockIdx.x * 256 + threadIdx.x;   // 0 .. 1048575
    int c4 = o & (NC4 - 1);
    int x  = (o >> 6) & (NW - 1);
    int y  = (o >> 12) & (NH - 1);
    int b  = o >> 18;

    int x1 = min(x + 1, NW - 1);
    int y1 = min(y + 1, NH - 1);

    const float4* base = fm + (size_t)b * NH * NW * NC4;
    float4 a  = __ldg(base + ((size_t)y  * NW + x ) * NC4 + c4);
    float4 bb = __ldg(base + ((size_t)y  * NW + x1) * NC4 + c4);
    float4 cc = __ldg(base + ((size_t)y1 * NW + x ) * NC4 + c4);
    float4 dd = __ldg(base + ((size_t)y1 * NW + x1) * NC4 + c4);

    g_q[o] = f4max(f4max(a, bb), f4max(cc, dd));
}

// ---------------- Kernel 2: gather, one CTA per (ph, r, b) ----------------
// Block (64 c4-lanes, 4 y-slices). Each slice strides the y-window list and
// keeps 7 per-pw accumulators; one smem reduction combines slices. ROI
// decode amortized over 7 bins, 8 warps/CTA keep the SM fed.
__global__ void __launch_bounds__(NC4 * NSL)
roipool_gather_kernel(const float* __restrict__ rois,
                      float4* __restrict__ out) {
    const int ph = blockIdx.x;           // 0..6
    const int r  = blockIdx.y;
    const int b  = blockIdx.z;
    const int c4 = threadIdx.x;          // 0..63
    const int sl = threadIdx.y;          // 0..3

    __shared__ float4 red[NSL][PW][NC4];

    const float* roi = rois + ((b * NR + r) << 2);
    const float y0f = __ldg(roi + 0);
    const float x0f = __ldg(roi + 1);
    const float y1f = __ldg(roi + 2);
    const float x1f = __ldg(roi + 3);

    // tf.cast(float->int) on non-negative values == floor
    const int h0 = (int)floorf((float)NH * y0f);
    const int w0 = (int)floorf((float)NW * x0f);
    const int h1 = (int)floorf((float)NH * y1f);
    const int w1 = (int)floorf((float)NW * x1f);
    const int rh = h1 - h0;
    const int rw = w1 - w0;
    const int hstep = max(rh / PH, 1);
    const int wstep = max(rw / PW, 1);

    // y range for this ph bin (all bin dims >= 2 for this problem's ROIs)
    const int ys = h0 + ph * hstep;
    const int Ly = (ph == PH - 1) ? (rh - (PH - 1) * hstep) : hstep;
    const int ny = (Ly + 1) >> 1;        // ceil(Ly/2) sliding 2-windows
    const int ylast = ys + Ly - 2;

    // x windows: bins 0..5 have length wstep; bin 6 has length rw-6*wstep
    const int nxf = (wstep + 1) >> 1;    // windows per full bin
    const int wlast_off = wstep - 2;     // local clamp inside a full bin
    const int xs6 = w0 + (PW - 1) * wstep;
    const int L6 = rw - (PW - 1) * wstep;
    const int nx6 = (L6 + 1) >> 1;
    const int xlast6 = w0 + rw - 2;

    const float4* qb = g_q + (size_t)b * NH * NW * NC4 + c4;

    float4 acc0 = make_float4(-INFINITY, -INFINITY, -INFINITY, -INFINITY);
    float4 acc1 = acc0, acc2 = acc0, acc3 = acc0, acc4 = acc0, acc5 = acc0, acc6 = acc0;

    for (int ky = sl; ky < ny; ky += NSL) {
        const int y = min(ys + (ky << 1), ylast);
        const float4* row = qb + (size_t)y * NW * NC4;

        for (int kx = 0; kx < nxf; ++kx) {
            const int xo = min(kx << 1, wlast_off);    // same offset for all 6 full bins
            const int x0b = w0 + xo;
            acc0 = f4max(acc0, __ldg(row + (size_t)(x0b            ) * NC4));
            acc1 = f4max(acc1, __ldg(row + (size_t)(x0b + wstep    ) * NC4));
            acc2 = f4max(acc2, __ldg(row + (size_t)(x0b + 2 * wstep) * NC4));
            acc3 = f4max(acc3, __ldg(row + (size_t)(x0b + 3 * wstep) * NC4));
            acc4 = f4max(acc4, __ldg(row + (size_t)(x0b + 4 * wstep) * NC4));
            acc5 = f4max(acc5, __ldg(row + (size_t)(x0b + 5 * wstep) * NC4));
        }
        #pragma unroll 2
        for (int kx = 0; kx < nx6; ++kx) {
            const int x = min(xs6 + (kx << 1), xlast6);
            acc6 = f4max(acc6, __ldg(row + (size_t)x * NC4));
        }
    }

    red[sl][0][c4] = acc0;
    red[sl][1][c4] = acc1;
    red[sl][2][c4] = acc2;
    red[sl][3][c4] = acc3;
    red[sl][4][c4] = acc4;
    red[sl][5][c4] = acc5;
    red[sl][6][c4] = acc6;
    __syncthreads();

    // slices 0..3 each finalize a subset of bins (sl handles bins sl, sl+4)
    float4* outp = out + (((size_t)(b * NR + r) * PH + ph) * PW) * NC4 + c4;
    for (int bin = sl; bin < PW; bin += NSL) {
        float4 v = f4max(f4max(red[0][bin][c4], red[1][bin][c4]),
                         f4max(red[2][bin][c4], red[3][bin][c4]));
        outp[(size_t)bin * NC4] = v;
    }
}

extern "C" void kernel_launch(void* const* d_in, const int* in_sizes, int n_in,
                              void* d_out, int out_size) {
    const float4* fm  = (const float4*)d_in[0];
    const float* rois = (const float*)d_in[1];
    float4* out       = (float4*)d_out;

    build_q_kernel<<<(NB * NH * NW * NC4) / 256, 256>>>(fm);
    dim3 grid2(PH, NR, NB);
    dim3 block2(NC4, NSL);
    roipool_gather_kernel<<<grid2, block2>>>(rois, out);
}

// round 12
// speedup vs baseline: 1.2443x; 1.2443x over previous
#include <cuda_runtime.h>
#include <math.h>

#define PH 7
#define PW 7
#define NB 4
#define NH 64
#define NW 64
#define NC 256
#define NR 128
#define NC4 (NC / 4)    // 64 float4 lanes per cell
#define NBINS (PH * PW) // 49
#define BUILD_BLKS ((NB * NH * NW * NC4) / 256)   // 4096
#define BOUND_BLKS ((NB * NR * NBINS) / 256)      // 98

// Scratch: sliding 2x2 max pyramid, q[b][y][x][c4] (float4) = max over
// fm[y..y+1][x..x+1] (clamped). 16 MB, L2-resident.
__device__ float4 g_q[NB * NH * NW * NC4];
// Packed bin bounds per (b, r, bin): x = ys | ylast<<8 | ny<<16,
//                                    y = xs | xlast<<8 | nx<<16.  200 KB.
__device__ int2 g_bounds[NB * NR * NBINS];

__device__ __forceinline__ float4 f4max(float4 a, float4 b) {
    float4 r;
    r.x = fmaxf(a.x, b.x);
    r.y = fmaxf(a.y, b.y);
    r.z = fmaxf(a.z, b.z);
    r.w = fmaxf(a.w, b.w);
    return r;
}

// ---- Kernel 1: build pyramid (blocks 0..4095) + bin bounds (tail blocks) ----
__global__ void __launch_bounds__(256)
build_kernel(const float4* __restrict__ fm, const float* __restrict__ rois) {
    if (blockIdx.x < BUILD_BLKS) {
        int o = blockIdx.x * 256 + threadIdx.x;   // 0 .. 1048575
        int c4 = o & (NC4 - 1);
        int x  = (o >> 6) & (NW - 1);
        int y  = (o >> 12) & (NH - 1);
        int b  = o >> 18;

        int x1 = min(x + 1, NW - 1);
        int y1 = min(y + 1, NH - 1);

        const float4* base = fm + (size_t)b * NH * NW * NC4;
        float4 a  = __ldg(base + ((size_t)y  * NW + x ) * NC4 + c4);
        float4 bb = __ldg(base + ((size_t)y  * NW + x1) * NC4 + c4);
        float4 cc = __ldg(base + ((size_t)y1 * NW + x ) * NC4 + c4);
        float4 dd = __ldg(base + ((size_t)y1 * NW + x1) * NC4 + c4);

        g_q[o] = f4max(f4max(a, bb), f4max(cc, dd));
    } else {
        // one thread per (b, r, bin): 98 blocks * 256 = 25088 exactly
        int idx = (blockIdx.x - BUILD_BLKS) * 256 + threadIdx.x;
        int bin = idx % NBINS;
        int rb  = idx / NBINS;          // b*NR + r
        int ph  = bin / PW;
        int pw  = bin % PW;

        const float* roi = rois + (rb << 2);
        // tf.cast(float->int) on non-negative values == floor
        const int h0 = (int)floorf((float)NH * __ldg(roi + 0));
        const int w0 = (int)floorf((float)NW * __ldg(roi + 1));
        const int h1 = (int)floorf((float)NH * __ldg(roi + 2));
        const int w1 = (int)floorf((float)NW * __ldg(roi + 3));
        const int rh = h1 - h0;
        const int rw = w1 - w0;
        const int hstep = max(rh / PH, 1);
        const int wstep = max(rw / PW, 1);

        int ys = h0 + ph * hstep;
        int ye = (ph == PH - 1) ? (h0 + rh) : min(ys + hstep, h0 + rh);
        int xs = w0 + pw * wstep;
        int xe = (pw == PW - 1) ? (w0 + rw) : min(xs + wstep, w0 + rw);

        // All bin dims >= 2 here (rh,rw >= 19 => step >= 2, last bin >= step).
        int ny = (ye - ys + 1) >> 1;     // ceil(Ly/2) sliding 2-windows
        int nx = (xe - xs + 1) >> 1;
        int ylast = ye - 2;
        int xlast = xe - 2;

        int2 bd;
        bd.x = ys | (ylast << 8) | (ny << 16);
        bd.y = xs | (xlast << 8) | (nx << 16);
        g_bounds[idx] = bd;
    }
}

// ---------------- Kernel 2: gather bins from pyramid ----------------
// One 64-thread block per (bin, r, b). Prologue is a single broadcast 8B
// bounds load + shifts; body is ~5 coalesced float4 loads from L2-resident q.
__global__ void __launch_bounds__(NC4)
roipool_gather_kernel(float4* __restrict__ out) {
    const int bin = blockIdx.x;          // 0..48
    const int r   = blockIdx.y;
    const int b   = blockIdx.z;
    const int c4  = threadIdx.x;

    const int rb = b * NR + r;
    const int2 bd = __ldg(&g_bounds[rb * NBINS + bin]);
    const int ys    = bd.x & 0xFF;
    const int ylast = (bd.x >> 8) & 0xFF;
    const int ny    = bd.x >> 16;
    const int xs    = bd.y & 0xFF;
    const int xlast = (bd.y >> 8) & 0xFF;
    const int nx    = bd.y >> 16;

    const float4* qb = g_q + (size_t)b * NH * NW * NC4 + c4;

    float4 acc = make_float4(-INFINITY, -INFINITY, -INFINITY, -INFINITY);
    for (int ky = 0; ky < ny; ++ky) {
        const int y = min(ys + (ky << 1), ylast);
        const float4* rowp = qb + (size_t)y * NW * NC4;
        #pragma unroll 3
        for (int kx = 0; kx < nx; ++kx) {
            const int x = min(xs + (kx << 1), xlast);
            acc = f4max(acc, __ldg(rowp + (size_t)x * NC4));
        }
    }

    out[((size_t)rb * NBINS + bin) * NC4 + c4] = acc;
}

extern "C" void kernel_launch(void* const* d_in, const int* in_sizes, int n_in,
                              void* d_out, int out_size) {
    const float4* fm  = (const float4*)d_in[0];
    const float* rois = (const float*)d_in[1];
    float4* out       = (float4*)d_out;

    build_kernel<<<BUILD_BLKS + BOUND_BLKS, 256>>>(fm, rois);
    dim3 grid2(NBINS, NR, NB);
    roipool_gather_kernel<<<grid2, NC4>>>(out);
}

// round 17
// speedup vs baseline: 1.3672x; 1.0987x over previous
#include <cuda_runtime.h>
#include <math.h>

#define PH 7
#define PW 7
#define NB 4
#define NH 64
#define NW 64
#define NC 256
#define NR 128
#define NC4 (NC / 4)    // 64 float4 lanes per cell
#define NBINS (PH * PW) // 49
#define BUILD_BLKS ((NB * (NH / 2) * NW * NC4) / 256)  // 2048 (2 rows/thread)
#define BOUND_BLKS ((NB * NR * NBINS) / 256)           // 98

// Sliding 2x2 max pyramid, q[b][y][x][c4] = max over fm[y..y+1][x..x+1]
// (clamped). 16 MB, L2-resident. Row stride = 64KB (<<16), x stride = 1KB (<<10).
__device__ float4 g_q[NB * NH * NW * NC4];
// Packed bin bounds per (b, r, bin): x = ys | ylast<<8 | ny<<16,
//                                    y = xs | xlast<<8 | nx<<16.  200 KB.
__device__ int2 g_bounds[NB * NR * NBINS];

__device__ __forceinline__ float4 f4max(float4 a, float4 b) {
    float4 r;
    r.x = fmaxf(a.x, b.x);
    r.y = fmaxf(a.y, b.y);
    r.z = fmaxf(a.z, b.z);
    r.w = fmaxf(a.w, b.w);
    return r;
}

// ---- Kernel 1: build pyramid (2 y-rows per thread) + bin bounds (tail) ----
__global__ void __launch_bounds__(256)
build_kernel(const float4* __restrict__ fm, const float* __restrict__ rois) {
    if (blockIdx.x < BUILD_BLKS) {
        int o  = blockIdx.x * 256 + threadIdx.x;   // 0 .. 524287
        int c4 = o & (NC4 - 1);
        int x  = (o >> 6) & (NW - 1);
        int yp = (o >> 12) & (NH / 2 - 1);         // y-pair index
        int b  = o >> 17;

        const int y0 = yp << 1;
        const int y1 = y0 + 1;
        const int y2 = min(y0 + 2, NH - 1);
        const int x1 = min(x + 1, NW - 1);

        const float4* base = fm + (size_t)b * NH * NW * NC4 + c4;
        float4 r0a = __ldg(base + ((size_t)y0 * NW + x ) * NC4);
        float4 r0b = __ldg(base + ((size_t)y0 * NW + x1) * NC4);
        float4 r1a = __ldg(base + ((size_t)y1 * NW + x ) * NC4);
        float4 r1b = __ldg(base + ((size_t)y1 * NW + x1) * NC4);
        float4 r2a = __ldg(base + ((size_t)y2 * NW + x ) * NC4);
        float4 r2b = __ldg(base + ((size_t)y2 * NW + x1) * NC4);

        float4 rm0 = f4max(r0a, r0b);
        float4 rm1 = f4max(r1a, r1b);
        float4 rm2 = f4max(r2a, r2b);

        float4* qp = g_q + ((size_t)b * NH + y0) * NW * NC4 + (size_t)x * NC4 + c4;
        qp[0]             = f4max(rm0, rm1);
        qp[NW * NC4]      = f4max(rm1, rm2);
    } else {
        // one thread per (b, r, bin): 98 blocks * 256 = 25088 exactly
        int idx = (blockIdx.x - BUILD_BLKS) * 256 + threadIdx.x;
        int bin = idx % NBINS;
        int rb  = idx / NBINS;          // b*NR + r
        int ph  = bin / PW;
        int pw  = bin % PW;

        const float* roi = rois + (rb << 2);
        // tf.cast(float->int) on non-negative values == floor
        const int h0 = (int)floorf((float)NH * __ldg(roi + 0));
        const int w0 = (int)floorf((float)NW * __ldg(roi + 1));
        const int h1 = (int)floorf((float)NH * __ldg(roi + 2));
        const int w1 = (int)floorf((float)NW * __ldg(roi + 3));
        const int rh = h1 - h0;
        const int rw = w1 - w0;
        const int hstep = max(rh / PH, 1);
        const int wstep = max(rw / PW, 1);

        int ys = h0 + ph * hstep;
        int ye = (ph == PH - 1) ? (h0 + rh) : min(ys + hstep, h0 + rh);
        int xs = w0 + pw * wstep;
        int xe = (pw == PW - 1) ? (w0 + rw) : min(xs + wstep, w0 + rw);

        // All bin dims >= 2 here (rh,rw >= 19 => step >= 2, last bin >= step).
        int ny = (ye - ys + 1) >> 1;     // ceil(Ly/2) sliding 2-windows
        int nx = (xe - xs + 1) >> 1;
        int ylast = ye - 2;
        int xlast = xe - 2;

        int2 bd;
        bd.x = ys | (ylast << 8) | (ny << 16);
        bd.y = xs | (xlast << 8) | (nx << 16);
        g_bounds[idx] = bd;
    }
}

// ---------------- Kernel 2: gather bins from pyramid ----------------
// 128-thread CTA covers 2 bins (warps 0-1 -> bin 2i, warps 2-3 -> bin 2i+1).
// Addressing is pure shift/min byte-offset arithmetic on the L2-resident q.
__global__ void __launch_bounds__(128)
roipool_gather_kernel(float4* __restrict__ out) {
    const int r  = blockIdx.y;
    const int b  = blockIdx.z;
    const int c4 = threadIdx.x & (NC4 - 1);
    const int bin = (blockIdx.x << 1) + (threadIdx.x >> 6);   // 0..49

    const int rb = b * NR + r;
    const int binc = min(bin, NBINS - 1);
    const int2 bd = __ldg(&g_bounds[rb * NBINS + binc]);

    const unsigned ys_off    = (unsigned)(bd.x & 0xFF) << 16;
    const unsigned ylast_off = (unsigned)((bd.x >> 8) & 0xFF) << 16;
    const int      ny        = bd.x >> 16;
    const unsigned xs_off    = (unsigned)(bd.y & 0xFF) << 10;
    const unsigned xlast_off = (unsigned)((bd.y >> 8) & 0xFF) << 10;
    const int      nx        = bd.y >> 16;

    const char* base = (const char*)(g_q + (size_t)b * NH * NW * NC4) + (c4 << 4);

    float4 acc = make_float4(-INFINITY, -INFINITY, -INFINITY, -INFINITY);
    unsigned yo = ys_off;
    for (int ky = 0; ky < ny; ++ky, yo += (2u << 16)) {
        const char* rp = base + min(yo, ylast_off);
        unsigned xo = xs_off;
        #pragma unroll 3
        for (int kx = 0; kx < nx; ++kx, xo += 2048u) {
            acc = f4max(acc, __ldg((const float4*)(rp + min(xo, xlast_off))));
        }
    }

    if (bin < NBINS)
        out[((size_t)rb * NBINS + bin) * NC4 + c4] = acc;
}

extern "C" void kernel_launch(void* const* d_in, const int* in_sizes, int n_in,
                              void* d_out, int out_size) {
    const float4* fm  = (const float4*)d_in[0];
    const float* rois = (const float*)d_in[1];
    float4* out       = (float4*)d_out;

    build_kernel<<<BUILD_BLKS + BOUND_BLKS, 256>>>(fm, rois);
    dim3 grid2((NBINS + 1) / 2, NR, NB);   // 25 x 128 x 4
    roipool_gather_kernel<<<grid2, 128>>>(out);
}